// round 1
// baseline (speedup 1.0000x reference)
#include <cuda_runtime.h>
#include <cuda_bf16.h>
#include <math.h>

#define MAXB 8192

// Per-batch penalties live in a device global (no allocations allowed).
__device__ float g_pen[MAXB];

// One CTA (64 threads) per 64x64 matrix.
// Builds M = lower-symmetrized (diag(deg) - sigmoid(E)), Householder-tridiagonalizes
// in shared memory, then finds lambda_2 via warp-parallel Sturm multisection.
__global__ __launch_bounds__(64) void spectral_solve_kernel(
    const float* __restrict__ E, int B)
{
    int b = blockIdx.x;
    if (b >= B) return;

    __shared__ float A[64][65];   // odd stride 65 -> conflict-free column access
    __shared__ float v[64], w[64], red[64];
    __shared__ float dd[64], ee[64], e2s[64];
    __shared__ float scal;
    __shared__ float lohi[2];

    const int t = threadIdx.x;
    const float* Eb = E + (size_t)b * 4096;

    // ---- Build A = sigmoid(E), row sums for degree ----
    float rs = 0.f;
    #pragma unroll 8
    for (int j = 0; j < 64; j++) {
        float x = Eb[t * 64 + j];
        float a = 1.f / (1.f + __expf(-x));
        A[t][j] = a;
        rs += a;
    }
    float diag = rs - A[t][t];   // deg_t - A[t][t]
    __syncthreads();

    // ---- Symmetrize from LOWER triangle with negation: M[i][j]=M[j][i]=-A[i][j], i>j ----
    // Thread t owns lower elements (t, j<t): writes (t,j) and mirror (j,t). No races:
    // each lower element written only by its row thread, each upper only by its column thread.
    for (int j = 0; j < t; j++) {
        float a = A[t][j];
        A[t][j] = -a;
        A[j][t] = -a;
    }
    A[t][t] = diag;
    __syncthreads();

    // ---- Householder tridiagonalization ----
    for (int k = 0; k < 62; k++) {
        const int m0 = k + 1;

        // sigma = || A[m0..63][k] ||^2
        float xi = (t >= m0) ? A[t][k] : 0.f;
        red[t] = xi * xi;
        __syncthreads();
        if (t < 32) red[t] += red[t + 32];
        __syncthreads();
        if (t < 32) {
            float s = red[t];
            #pragma unroll
            for (int o = 16; o > 0; o >>= 1) s += __shfl_down_sync(0xffffffffu, s, o);
            if (t == 0) scal = s;
        }
        __syncthreads();
        float sigma = scal;
        float x0    = A[m0][k];
        float normx = sqrtf(sigma);
        bool  skip  = (normx < 1e-18f);      // uniform across block (from shared scal)
        float alpha = (x0 >= 0.f) ? -normx : normx;

        if (t == 0) { dd[k] = A[k][k]; ee[k] = skip ? 0.f : alpha; }

        if (!skip) {
            // v = x + sign(x0)*||x||*e1 ; beta = 2/(v'v) = 1/(||x||(||x||+|x0|))
            float beta = 1.f / (normx * (normx + fabsf(x0)));
            v[t] = (t > m0) ? xi : ((t == m0) ? (x0 - alpha) : 0.f);
            __syncthreads();

            // p = beta * A v (trailing block only)
            float p = 0.f;
            if (t >= m0) {
                for (int j = m0; j < 64; j++) p += A[t][j] * v[j];
                p *= beta;
            }

            // K = 0.5 * v'p
            red[t] = v[t] * p;
            __syncthreads();
            if (t < 32) red[t] += red[t + 32];
            __syncthreads();
            if (t < 32) {
                float s = red[t];
                #pragma unroll
                for (int o = 16; o > 0; o >>= 1) s += __shfl_down_sync(0xffffffffu, s, o);
                if (t == 0) scal = s;
            }
            __syncthreads();
            float K = 0.5f * scal;
            w[t] = p - K * v[t];
            __syncthreads();

            // A <- A - v w' - w v'  (trailing block)
            if (t >= m0) {
                float vt = v[t], wt = w[t];
                for (int j = m0; j < 64; j++)
                    A[t][j] -= vt * w[j] + wt * v[j];
            }
            __syncthreads();
        }
    }

    if (t == 0) {
        dd[62] = A[62][62];
        dd[63] = A[63][63];
        ee[62] = A[63][62];
        ee[63] = 0.f;
    }
    __syncthreads();

    e2s[t] = (t < 63) ? ee[t] * ee[t] : 0.f;

    // ---- Gershgorin bounds ----
    float r = ((t > 0) ? fabsf(ee[t - 1]) : 0.f) + ((t < 63) ? fabsf(ee[t]) : 0.f);
    red[t] = dd[t] - r;
    __syncthreads();
    if (t < 32) red[t] = fminf(red[t], red[t + 32]);
    __syncthreads();
    if (t < 32) {
        float s = red[t];
        #pragma unroll
        for (int o = 16; o > 0; o >>= 1) s = fminf(s, __shfl_down_sync(0xffffffffu, s, o));
        if (t == 0) lohi[0] = s;
    }
    __syncthreads();
    red[t] = dd[t] + r;
    __syncthreads();
    if (t < 32) red[t] = fmaxf(red[t], red[t + 32]);
    __syncthreads();
    if (t < 32) {
        float s = red[t];
        #pragma unroll
        for (int o = 16; o > 0; o >>= 1) s = fmaxf(s, __shfl_down_sync(0xffffffffu, s, o));
        if (t == 0) lohi[1] = s;
    }
    __syncthreads();

    // ---- Warp-parallel multisection for lambda_2 (Sturm counts) ----
    if (t < 32) {
        float lo = lohi[0], hi = lohi[1];
        #pragma unroll 1
        for (int round = 0; round < 5; round++) {
            float stepw = (hi - lo) * (1.f / 33.f);
            float x = lo + stepw * (float)(t + 1);
            // count eigenvalues < x
            int cnt = 0;
            float q = dd[0] - x;
            if (q < 0.f) cnt++;
            #pragma unroll 1
            for (int i = 1; i < 64; i++) {
                float denom = q;
                if (fabsf(denom) < 1e-25f) denom = (denom < 0.f) ? -1e-25f : 1e-25f;
                q = (dd[i] - x) - __fdividef(e2s[i - 1], denom);
                if (q < 0.f) cnt++;
            }
            unsigned bal = __ballot_sync(0xffffffffu, cnt >= 2);
            if (bal == 0u) {
                lo = lo + stepw * 32.f;            // lambda_2 above all samples
            } else {
                int j = __ffs(bal) - 1;            // first lane with cnt >= 2
                float nhi = lo + stepw * (float)(j + 1);
                float nlo = (j > 0) ? (lo + stepw * (float)j) : lo;
                hi = nhi; lo = nlo;
            }
        }
        if (t == 0) {
            float lam2 = 0.5f * (lo + hi);
            float p = 0.1f - lam2;
            g_pen[b] = (p > 0.f) ? p : 0.f;
        }
    }
}

// Deterministic reduction: fixed strided order per thread + fixed tree.
__global__ __launch_bounds__(256) void spectral_reduce_kernel(float* __restrict__ out, int B)
{
    __shared__ float red[256];
    int t = threadIdx.x;
    float s = 0.f;
    for (int i = t; i < B; i += 256) s += g_pen[i];
    red[t] = s;
    __syncthreads();
    #pragma unroll
    for (int o = 128; o >= 1; o >>= 1) {
        if (t < o) red[t] += red[t + o];
        __syncthreads();
    }
    if (t == 0) out[0] = red[0] / (float)B;
}

extern "C" void kernel_launch(void* const* d_in, const int* in_sizes, int n_in,
                              void* d_out, int out_size)
{
    const float* E = (const float*)d_in[0];
    // d_in[1] = node_types (int64) — unused by the reference computation.
    int B = in_sizes[0] / 4096;   // 64*64 per matrix
    if (B > MAXB) B = MAXB;

    spectral_solve_kernel<<<B, 64>>>(E, B);
    spectral_reduce_kernel<<<1, 256>>>((float*)d_out, B);
}

// round 3
// speedup vs baseline: 1.6289x; 1.6289x over previous
#include <cuda_runtime.h>
#include <cuda_bf16.h>
#include <math.h>

#define MAXB 8192
#define WPC 4   // warps (matrices) per CTA

__device__ float g_pen[MAXB];

__device__ __forceinline__ float sg(float x) { return 1.f / (1.f + __expf(-x)); }

// One WARP per 64x64 matrix. Each lane holds rows (lane) and (lane+32) in registers.
// Householder tridiagonalization fully in registers; v/w/d/e via per-warp shared.
// No __syncthreads anywhere — warps are independent.
__global__ void __launch_bounds__(32 * WPC)
spectral_solve_kernel(const float* __restrict__ E, int B)
{
    const int lane = threadIdx.x & 31;
    const int w    = threadIdx.x >> 5;
    const int b    = blockIdx.x * WPC + w;
    if (b >= B) return;

    __shared__ __align__(16) float sv [WPC][64];
    __shared__ __align__(16) float sw_[WPC][64];
    __shared__ float sdd[WPC][64];
    __shared__ float see[WPC][64];

    const int rL = lane, rH = lane + 32;
    const float* Eb = E + (size_t)b * 4096;

    float aL[64], aH[64];

    // ---- Pass 1: own rows (contiguous), sigmoid, degree, lower-triangle fill ----
    float degL = 0.f, degH = 0.f, dsL = 0.f, dsH = 0.f;
    #pragma unroll
    for (int j0 = 0; j0 < 64; j0 += 4) {
        float4 eL = *(const float4*)(Eb + (size_t)rL * 64 + j0);
        float4 eH = *(const float4*)(Eb + (size_t)rH * 64 + j0);
        float s;
        s = sg(eL.x); degL += s; if (j0+0 <  rL) aL[j0+0] = -s; if (j0+0 == rL) dsL = s;
        s = sg(eL.y); degL += s; if (j0+1 <  rL) aL[j0+1] = -s; if (j0+1 == rL) dsL = s;
        s = sg(eL.z); degL += s; if (j0+2 <  rL) aL[j0+2] = -s; if (j0+2 == rL) dsL = s;
        s = sg(eL.w); degL += s; if (j0+3 <  rL) aL[j0+3] = -s; if (j0+3 == rL) dsL = s;
        s = sg(eH.x); degH += s; if (j0+0 <  rH) aH[j0+0] = -s; if (j0+0 == rH) dsH = s;
        s = sg(eH.y); degH += s; if (j0+1 <  rH) aH[j0+1] = -s; if (j0+1 == rH) dsH = s;
        s = sg(eH.z); degH += s; if (j0+2 <  rH) aH[j0+2] = -s; if (j0+2 == rH) dsH = s;
        s = sg(eH.w); degH += s; if (j0+3 <  rH) aH[j0+3] = -s; if (j0+3 == rH) dsH = s;
    }

    // ---- Pass 2: upper triangle from transposed reads (coalesced across lanes) ----
    #pragma unroll
    for (int j = 1; j < 64; j++) {
        float eu = Eb[(size_t)j * 64 + rL];        // warp-coalesced at fixed j
        if (j > rL) aL[j] = -sg(eu);
        if (j >= 33) {
            float eu2 = Eb[(size_t)j * 64 + rH];
            if (j > rH) aH[j] = -sg(eu2);
        }
    }

    // ---- Diagonal: deg - sigma(E[r][r]) (predicated static-index writes) ----
    {
        float dL = degL - dsL, dH = degH - dsH;
        #pragma unroll
        for (int j = 0; j < 64; j++) {
            if (j == rL) aL[j] = dL;
            if (j == rH) aH[j] = dH;
        }
    }

    // ---- Householder tridiagonalization (62 steps), matrix in registers ----
    float xiL = aL[0];   // current column k: element k of own row (symmetric matrix)
    float xiH = aH[0];

    for (int k = 0; k < 62; k++) {
        const int m0 = k + 1;

        // sigma = sum_{t>=m0} A[t][k]^2   (warp allreduce)
        float cL = (rL >= m0) ? xiL : 0.f;
        float cH = (rH >= m0) ? xiH : 0.f;
        float sig = cL * cL + cH * cH;
        #pragma unroll
        for (int o = 16; o > 0; o >>= 1) sig += __shfl_xor_sync(0xffffffffu, sig, o);

        // x0 = A[m0][k] broadcast from owner lane
        float cand = (m0 < 32) ? xiL : xiH;
        float x0 = __shfl_sync(0xffffffffu, cand, m0 & 31);

        float normx = sqrtf(sig);
        bool  skip  = (normx < 1e-18f);
        float alpha = (x0 >= 0.f) ? -normx : normx;
        float beta  = skip ? 0.f : 1.f / (normx * (normx + fabsf(x0)));

        if (lane == 0) see[w][k] = skip ? 0.f : alpha;
        if (rL == k)   sdd[w][k] = xiL;     // final diagonal of retired row k
        if (rH == k)   sdd[w][k] = xiH;

        float vL = (rL > m0) ? xiL : ((rL == m0) ? (x0 - alpha) : 0.f);
        float vH = (rH > m0) ? xiH : ((rH == m0) ? (x0 - alpha) : 0.f);
        sv[w][rL] = vL;
        sv[w][rH] = vH;
        __syncwarp();

        // p = beta * A v  (trailing rows only; v[j]=0 for j<m0 makes chunks safe)
        const int c0 = m0 >> 4;
        float pL0 = 0.f, pL1 = 0.f, pH0 = 0.f, pH1 = 0.f;
        #pragma unroll
        for (int c = 0; c < 4; c++) {
            if (c >= c0) {
                #pragma unroll
                for (int u = 0; u < 16; u += 4) {
                    const int j = 16 * c + u;
                    float4 v4 = *(const float4*)&sv[w][j];
                    pL0 += aL[j]     * v4.x + aL[j + 1] * v4.y;
                    pL1 += aL[j + 2] * v4.z + aL[j + 3] * v4.w;
                    pH0 += aH[j]     * v4.x + aH[j + 1] * v4.y;
                    pH1 += aH[j + 2] * v4.z + aH[j + 3] * v4.w;
                }
            }
        }
        float pL = (rL >= m0) ? (pL0 + pL1) * beta : 0.f;
        float pH = (rH >= m0) ? (pH0 + pH1) * beta : 0.f;

        // K = 0.5 v'p  (warp allreduce)
        float Ks = vL * pL + vH * pH;
        #pragma unroll
        for (int o = 16; o > 0; o >>= 1) Ks += __shfl_xor_sync(0xffffffffu, Ks, o);
        float K  = 0.5f * Ks;
        float wL = pL - K * vL;
        float wH = pH - K * vH;
        __syncwarp();
        sw_[w][rL] = wL;
        sw_[w][rH] = wH;
        __syncwarp();

        // A <- A - v w' - w v'  (registers), capturing next column a[m0] on the fly.
        float nL = 0.f, nH = 0.f;
        #pragma unroll
        for (int c = 0; c < 4; c++) {
            if (c >= c0) {
                #pragma unroll
                for (int u = 0; u < 16; u += 4) {
                    const int j = 16 * c + u;
                    float4 v4 = *(const float4*)&sv[w][j];
                    float4 w4 = *(const float4*)&sw_[w][j];
                    float t;
                    t = aL[j]   - (vL * w4.x + wL * v4.x); aL[j]   = t; if (j     == m0) nL = t;
                    t = aL[j+1] - (vL * w4.y + wL * v4.y); aL[j+1] = t; if (j + 1 == m0) nL = t;
                    t = aL[j+2] - (vL * w4.z + wL * v4.z); aL[j+2] = t; if (j + 2 == m0) nL = t;
                    t = aL[j+3] - (vL * w4.w + wL * v4.w); aL[j+3] = t; if (j + 3 == m0) nL = t;
                    t = aH[j]   - (vH * w4.x + wH * v4.x); aH[j]   = t; if (j     == m0) nH = t;
                    t = aH[j+1] - (vH * w4.y + wH * v4.y); aH[j+1] = t; if (j + 1 == m0) nH = t;
                    t = aH[j+2] - (vH * w4.z + wH * v4.z); aH[j+2] = t; if (j + 2 == m0) nH = t;
                    t = aH[j+3] - (vH * w4.w + wH * v4.w); aH[j+3] = t; if (j + 3 == m0) nH = t;
                }
            }
        }
        xiL = nL;
        xiH = nH;
        __syncwarp();   // sv/sw_ will be overwritten next iteration
    }

    // ---- Tail of tridiagonal: d[62], d[63], e[62] ----
    if (rH == 62) sdd[w][62] = xiH;                 // A[62][62]
    if (rH == 63) {
        see[w][62] = xiH;                           // A[63][62]
        sdd[w][63] = aH[63];                        // A[63][63] (static index)
        see[w][63] = 0.f;
    }
    __syncwarp();

    // e^2 into sw_ (reuse)
    sw_[w][rL] = see[w][rL] * see[w][rL];
    sw_[w][rH] = see[w][rH] * see[w][rH];
    __syncwarp();

    // ---- Gershgorin bounds (warp allreduce min/max) ----
    float dLv = sdd[w][rL], dHv = sdd[w][rH];
    float radL = ((rL > 0) ? fabsf(see[w][rL - 1]) : 0.f) + fabsf(see[w][rL]);
    float radH = fabsf(see[w][rH - 1]) + ((rH < 63) ? fabsf(see[w][rH]) : 0.f);
    float lo = fminf(dLv - radL, dHv - radH);
    float hi = fmaxf(dLv + radL, dHv + radH);
    #pragma unroll
    for (int o = 16; o > 0; o >>= 1) {
        lo = fminf(lo, __shfl_xor_sync(0xffffffffu, lo, o));
        hi = fmaxf(hi, __shfl_xor_sync(0xffffffffu, hi, o));
    }

    // ---- Warp-parallel multisection for lambda_2 (Sturm counts) ----
    #pragma unroll 1
    for (int round = 0; round < 5; round++) {
        float stepw = (hi - lo) * (1.f / 33.f);
        float x = lo + stepw * (float)(lane + 1);
        int cnt = 0;
        float q = sdd[w][0] - x;
        if (q < 0.f) cnt++;
        #pragma unroll 1
        for (int i = 1; i < 64; i++) {
            float denom = q;
            if (fabsf(denom) < 1e-25f) denom = (denom < 0.f) ? -1e-25f : 1e-25f;
            q = (sdd[w][i] - x) - __fdividef(sw_[w][i - 1], denom);
            if (q < 0.f) cnt++;
        }
        unsigned bal = __ballot_sync(0xffffffffu, cnt >= 2);
        if (bal == 0u) {
            lo = lo + stepw * 32.f;
        } else {
            int j = __ffs(bal) - 1;
            float nhi = lo + stepw * (float)(j + 1);
            float nlo = (j > 0) ? (lo + stepw * (float)j) : lo;
            hi = nhi; lo = nlo;
        }
    }
    if (lane == 0) {
        float lam2 = 0.5f * (lo + hi);
        float p = 0.1f - lam2;
        g_pen[b] = (p > 0.f) ? p : 0.f;
    }
}

// Deterministic final reduction.
__global__ void __launch_bounds__(256)
spectral_reduce_kernel(float* __restrict__ out, int B)
{
    __shared__ float red[256];
    int t = threadIdx.x;
    float s = 0.f;
    for (int i = t; i < B; i += 256) s += g_pen[i];
    red[t] = s;
    __syncthreads();
    #pragma unroll
    for (int o = 128; o >= 1; o >>= 1) {
        if (t < o) red[t] += red[t + o];
        __syncthreads();
    }
    if (t == 0) out[0] = red[0] / (float)B;
}

extern "C" void kernel_launch(void* const* d_in, const int* in_sizes, int n_in,
                              void* d_out, int out_size)
{
    const float* E = (const float*)d_in[0];
    int B = in_sizes[0] / 4096;
    if (B > MAXB) B = MAXB;

    int grid = (B + WPC - 1) / WPC;
    spectral_solve_kernel<<<grid, 32 * WPC>>>(E, B);
    spectral_reduce_kernel<<<1, 256>>>((float*)d_out, B);
}